// round 12
// baseline (speedup 1.0000x reference)
#include <cuda_runtime.h>
#include <math.h>

#define Bn   16
#define Cn   256
#define Hn   128
#define Wn   128
#define HWn  (Hn * Wn)      // 16384
#define Kn   300
#define TOT4 (Bn * HWn / 4) // 65536 float4 pixel-groups
#define GRID 148            // one balanced block per SM

#define SEG   416           // per-warp survivor segment (16*416 = 6656 slots)
#define NV2   13            // phase-B values per thread (512*13 = 6656)
#define STOPC 400           // phase-B early stop (sort cost ~ M^2)
#define CAPF  464           // final candidate capacity

// Scratch (allocation-free rule: __device__ globals). 4 MB -> L2-resident.
__device__ float    g_reg0 [Bn * HWn];
__device__ float    g_reg1 [Bn * HWn];
__device__ float    g_conf [Bn * HWn];
__device__ unsigned g_sbits[Bn * HWn];

// ---------------------------------------------------------------------------
// Pass 1: fused 1x1 convs + sigmoid + score. One thread = 4 pixels (float4).
// 148 blocks x 512 threads, arithmetically balanced spans: every SM gets an
// equal share of the 65536 groups (no ragged wave, no idle SMs). HBM-bound.
// ---------------------------------------------------------------------------
__global__ __launch_bounds__(512) void score_kernel(
    const float* __restrict__ x,
    const float* __restrict__ w_reg,
    const float* __restrict__ b_reg,
    const float* __restrict__ w_conf,
    const float* __restrict__ b_conf)
{
    __shared__ float wr0[Cn], wr1[Cn], wc[Cn];
    if (threadIdx.x < Cn) {
        wr0[threadIdx.x] = w_reg[threadIdx.x];
        wr1[threadIdx.x] = w_reg[Cn + threadIdx.x];
        wc[threadIdx.x]  = w_conf[threadIdx.x];
    }
    __syncthreads();

    const int s = (int)(((long long)TOT4 * blockIdx.x) / GRID);
    const int e = (int)(((long long)TOT4 * (blockIdx.x + 1)) / GRID);

    const float br0 = __ldg(b_reg), br1 = __ldg(b_reg + 1), bc = __ldg(b_conf);

    for (int g4 = s + threadIdx.x; g4 < e; g4 += 512) {
        const int b = g4 >> 12;          // / (HWn/4)
        const int g = g4 & 4095;         // % (HWn/4)

        const float4* xp = reinterpret_cast<const float4*>(x)
                           + (size_t)b * Cn * (HWn / 4) + g;

        float4 a0 = make_float4(0.f, 0.f, 0.f, 0.f);
        float4 a1 = make_float4(0.f, 0.f, 0.f, 0.f);
        float4 a2 = make_float4(0.f, 0.f, 0.f, 0.f);

        #pragma unroll 16
        for (int c = 0; c < Cn; ++c) {
            // evict-first streaming load: don't thrash L2 (scratch lives there)
            float4 xv = __ldcs(&xp[(size_t)c * (HWn / 4)]);
            float u0 = wr0[c], u1 = wr1[c], u2 = wc[c];
            a0.x = fmaf(xv.x, u0, a0.x); a0.y = fmaf(xv.y, u0, a0.y);
            a0.z = fmaf(xv.z, u0, a0.z); a0.w = fmaf(xv.w, u0, a0.w);
            a1.x = fmaf(xv.x, u1, a1.x); a1.y = fmaf(xv.y, u1, a1.y);
            a1.z = fmaf(xv.z, u1, a1.z); a1.w = fmaf(xv.w, u1, a1.w);
            a2.x = fmaf(xv.x, u2, a2.x); a2.y = fmaf(xv.y, u2, a2.y);
            a2.z = fmaf(xv.z, u2, a2.z); a2.w = fmaf(xv.w, u2, a2.w);
        }

        float4 r0v, r1v, cfv; uint4 sbv;
        const float* p0 = &a0.x; const float* p1 = &a1.x; const float* p2 = &a2.x;
        float*       q0 = &r0v.x; float*      q1 = &r1v.x; float*      qc = &cfv.x;
        unsigned*    qs = &sbv.x;
        #pragma unroll
        for (int i = 0; i < 4; ++i) {
            float r0 = p0[i] + br0;
            float r1 = p1[i] + br1;
            float cf = 1.0f / (1.0f + expf(-(p2[i] + bc)));
            float sc = sqrtf(fmaf(r0, r0, r1 * r1)) * cf;
            q0[i] = r0; q1[i] = r1; qc[i] = cf; qs[i] = __float_as_uint(sc);
        }

        const int v = b * (HWn / 4) + g;   // float4-granular index
        reinterpret_cast<float4*>(g_reg0)[v] = r0v;
        reinterpret_cast<float4*>(g_reg1)[v] = r1v;
        reinterpret_cast<float4*>(g_conf)[v] = cfv;
        reinterpret_cast<uint4*>(g_sbits)[v] = sbv;
    }
}

// ---------------------------------------------------------------------------
// Pass 2: per-batch exact top-300 (jax.lax.top_k semantics: descending value,
// ties -> lower index). Hierarchical selection:
//
//  A) Per-warp MSB-down radix bisection (NO block barriers): each warp finds
//     P_w with count_w(>=P_w) in [300, ~384] over its 1024 values using only
//     __reduce_add_sync. Safety: a global-top-300 element x in warp w with
//     x < P_w would imply >=300 warp-w values above x -> rank(x) > 300.
//     So the union of per-warp survivors is a superset of the global top-300.
//  B) Ballot-compact survivors (~16*300-380) to SMEM (bits + u16 idx).
//  C) Block bisection on the compacted <=6656 values, 2 bits/iteration
//     (3 thresholds, packed counts), early stop at count <= 400.
//  D) Stable O(M^2) rank sort on 64-bit keys (bits<<32 | HWn-idx) + gather.
// ---------------------------------------------------------------------------
__global__ __launch_bounds__(512) void topk_kernel(float* __restrict__ out)
{
    const int b    = blockIdx.x;
    const int tid  = threadIdx.x;
    const int wid  = tid >> 5;
    const int lane = tid & 31;
    const unsigned* sb = g_sbits + b * HWn;

    __shared__ unsigned       sbit2[16 * SEG];
    __shared__ unsigned short sidx2[16 * SEG];
    __shared__ int            scnt [16];
    __shared__ unsigned       wc12 [16];
    __shared__ unsigned       wc3  [16];
    __shared__ unsigned       s_P;
    __shared__ int            s_cnt, s_done, s_m;
    __shared__ unsigned long long ckey[CAPF];

    if (tid == 0) { s_P = 0u; s_cnt = 1 << 20; s_done = 0; s_m = 0; }

    // ---- load: warp w owns indices [w*1024, w*1024+1024), uint4 loads ----
    unsigned v[32];
    {
        const uint4* p = reinterpret_cast<const uint4*>(sb + wid * 1024) + lane;
        #pragma unroll
        for (int j = 0; j < 8; ++j) {
            uint4 q = p[j * 32];
            v[j * 4 + 0] = q.x; v[j * 4 + 1] = q.y;
            v[j * 4 + 2] = q.z; v[j * 4 + 3] = q.w;
        }
    }
    // element jj (0..31) has original index: wid*1024 + (jj>>2)*128 + lane*4 + (jj&3)

    // ---- Phase A: per-warp bisection (no block syncs) ----
    unsigned Pw = 0u;
    for (int bit = 30; bit >= 0; --bit) {
        const unsigned T = Pw | (1u << bit);
        int c = 0;
        #pragma unroll
        for (int jj = 0; jj < 32; ++jj) c += (v[jj] >= T);
        c = __reduce_add_sync(0xFFFFFFFFu, c);
        if (c >= Kn) { Pw = T; if (c <= 384) break; }
    }

    // ---- Phase B prep: ballot-compact warp survivors into SMEM segment ----
    {
        const int base = wid * SEG;
        int pos = 0;
        #pragma unroll
        for (int jj = 0; jj < 32; ++jj) {
            const bool keep = (v[jj] >= Pw);
            const unsigned m = __ballot_sync(0xFFFFFFFFu, keep);
            if (keep) {
                const int q = pos + __popc(m & ((1u << lane) - 1u));
                if (q < SEG) {
                    sbit2[base + q] = v[jj];
                    sidx2[base + q] = (unsigned short)
                        (wid * 1024 + (jj >> 2) * 128 + lane * 4 + (jj & 3));
                }
            }
            pos += __popc(m);
        }
        if (lane == 0) scnt[wid] = (pos < SEG) ? pos : SEG;
    }
    __syncthreads();

    // ---- Phase B: block bisection on compacted values, 2 bits/iter ----
    unsigned u[NV2];
    #pragma unroll
    for (int j = 0; j < NV2; ++j) {
        const int sslot = tid + j * 512;              // < 6656
        const int sg    = sslot / SEG;
        const int pp    = sslot - sg * SEG;
        u[j] = (pp < scnt[sg]) ? sbit2[sslot] : 0u;
    }

    unsigned P = 0u;
    for (int hb = 30; hb >= 0; hb -= 2) {
        const unsigned T1 = P | (1u << hb);                          // hi
        const unsigned T2 = (hb > 0) ? (T1 | (1u << (hb - 1))) : T1; // hi+lo
        const unsigned T3 = (hb > 0) ? (P  | (1u << (hb - 1))) : T1; // lo
        int c1 = 0, c2 = 0, c3 = 0;
        #pragma unroll
        for (int j = 0; j < NV2; ++j) {
            c1 += (u[j] >= T1); c2 += (u[j] >= T2); c3 += (u[j] >= T3);
        }
        unsigned p12 = (unsigned)c1 | ((unsigned)c2 << 16);
        p12 = __reduce_add_sync(0xFFFFFFFFu, p12);
        int r3 = __reduce_add_sync(0xFFFFFFFFu, c3);
        if (lane == 0) { wc12[wid] = p12; wc3[wid] = (unsigned)r3; }
        __syncthreads();
        if (wid == 0) {
            unsigned a = (lane < 16) ? wc12[lane] : 0u;
            unsigned d = (lane < 16) ? wc3 [lane] : 0u;
            a = __reduce_add_sync(0xFFFFFFFFu, a);
            d = __reduce_add_sync(0xFFFFFFFFu, d);
            if (lane == 0) {
                const int C1 = (int)(a & 0xFFFFu);
                const int C2 = (int)(a >> 16);
                const int C3 = (int)d;
                if      (C2 >= Kn) { s_P = T2; s_cnt = C2; }
                else if (C1 >= Kn) { s_P = T1; s_cnt = C1; }
                else if (C3 >= Kn) { s_P = T3; s_cnt = C3; }
                if (s_cnt <= STOPC) s_done = 1;
            }
        }
        __syncthreads();
        P = s_P;
        if (s_done) break;
    }

    // ---- collect final candidates (>= P) with (bits, idx) keys ----
    #pragma unroll
    for (int j = 0; j < NV2; ++j) {
        if (u[j] >= P) {
            const int p = atomicAdd(&s_m, 1);
            if (p < CAPF) {
                const int sslot = tid + j * 512;
                const int idx = (int)sidx2[sslot];
                ckey[p] = ((unsigned long long)u[j] << 32)
                        | (unsigned)(HWn - idx);   // smaller idx => bigger key
            }
        }
    }
    __syncthreads();
    const int M = (s_m < CAPF) ? s_m : CAPF;

    // ---- stable rank sort (broadcast SMEM reads) + gather + write ----
    for (int i = tid; i < M; i += 512) {
        const unsigned long long mk = ckey[i];
        int rank = 0;
        #pragma unroll 4
        for (int j = 0; j < M; ++j) rank += (ckey[j] > mk);
        if (rank < Kn) {
            const int k = HWn - (int)(mk & 0xFFFFFFFFu);
            float* o = out + ((size_t)b * Kn + rank) * 3;
            o[0] = (float)(k / Hn) + g_reg0[b * HWn + k];
            o[1] = (float)(k % Hn) + g_reg1[b * HWn + k];
            o[2] = g_conf[b * HWn + k];
        }
    }
}

// ---------------------------------------------------------------------------
extern "C" void kernel_launch(void* const* d_in, const int* in_sizes, int n_in,
                              void* d_out, int out_size)
{
    const float* x      = (const float*)d_in[0];  // (16,256,128,128)
    const float* w_reg  = (const float*)d_in[1];  // (2,256)
    const float* b_reg  = (const float*)d_in[2];  // (2,)
    const float* w_conf = (const float*)d_in[3];  // (1,256)
    const float* b_conf = (const float*)d_in[4];  // (1,)
    float*       out    = (float*)d_out;          // (16,300,3)

    score_kernel<<<GRID, 512>>>(x, w_reg, b_reg, w_conf, b_conf);
    topk_kernel<<<Bn, 512>>>(out);
}

// round 13
// speedup vs baseline: 1.2821x; 1.2821x over previous
#include <cuda_runtime.h>
#include <math.h>

#define Bn   16
#define Cn   256
#define Hn   128
#define Wn   128
#define HWn  (Hn * Wn)      // 16384
#define Kn   300
#define SEGS 8              // selection segments per batch
#define SEGN (HWn / SEGS)   // 2048
#define SCAP 448            // per-segment candidate capacity (expect ~302)
#define CAPF 384            // final candidate capacity (expect ~302)
#define NS2  7              // stage2 slots per thread: 8*448/512

// Scratch (allocation-free rule: __device__ globals). ~4.2 MB -> L2-resident.
__device__ float    g_reg0 [Bn * HWn];
__device__ float    g_reg1 [Bn * HWn];
__device__ float    g_conf [Bn * HWn];
__device__ unsigned g_sbits[Bn * HWn];
__device__ unsigned long long g_cand[Bn * SEGS * SCAP];
__device__ int                g_ccnt[Bn * SEGS];

// ---------------------------------------------------------------------------
// Pass 1: fused 1x1 convs + sigmoid + score. One thread = 4 pixels (float4).
// EXACT R9 configuration (256 blocks x 256 threads, unroll 8): measured
// 60.4us / ~4.5 TB/s. Do not touch.
// ---------------------------------------------------------------------------
__global__ __launch_bounds__(256) void score_kernel(
    const float* __restrict__ x,
    const float* __restrict__ w_reg,
    const float* __restrict__ b_reg,
    const float* __restrict__ w_conf,
    const float* __restrict__ b_conf)
{
    __shared__ float wr0[Cn], wr1[Cn], wc[Cn];
    for (int i = threadIdx.x; i < Cn; i += 256) {
        wr0[i] = w_reg[i];
        wr1[i] = w_reg[Cn + i];
        wc[i]  = w_conf[i];
    }
    __syncthreads();

    const int gid = blockIdx.x * 256 + threadIdx.x;     // pixel-group id
    const int b   = gid >> 12;                          // / (HWn/4)
    const int g   = gid & 4095;                         // % (HWn/4)

    const float4* xp = reinterpret_cast<const float4*>(x)
                       + (size_t)b * Cn * (HWn / 4) + g;

    float4 a0 = make_float4(0.f, 0.f, 0.f, 0.f);
    float4 a1 = make_float4(0.f, 0.f, 0.f, 0.f);
    float4 a2 = make_float4(0.f, 0.f, 0.f, 0.f);

    #pragma unroll 8
    for (int c = 0; c < Cn; ++c) {
        // evict-first streaming load: don't thrash L2 (scratch lives there)
        float4 xv = __ldcs(&xp[(size_t)c * (HWn / 4)]);
        float u0 = wr0[c], u1 = wr1[c], u2 = wc[c];
        a0.x = fmaf(xv.x, u0, a0.x); a0.y = fmaf(xv.y, u0, a0.y);
        a0.z = fmaf(xv.z, u0, a0.z); a0.w = fmaf(xv.w, u0, a0.w);
        a1.x = fmaf(xv.x, u1, a1.x); a1.y = fmaf(xv.y, u1, a1.y);
        a1.z = fmaf(xv.z, u1, a1.z); a1.w = fmaf(xv.w, u1, a1.w);
        a2.x = fmaf(xv.x, u2, a2.x); a2.y = fmaf(xv.y, u2, a2.y);
        a2.z = fmaf(xv.z, u2, a2.z); a2.w = fmaf(xv.w, u2, a2.w);
    }

    const float br0 = __ldg(b_reg), br1 = __ldg(b_reg + 1), bc = __ldg(b_conf);

    float4 r0v, r1v, cfv; uint4 sbv;
    const float* p0 = &a0.x; const float* p1 = &a1.x; const float* p2 = &a2.x;
    float*       q0 = &r0v.x; float*      q1 = &r1v.x; float*      qc = &cfv.x;
    unsigned*    qs = &sbv.x;
    #pragma unroll
    for (int i = 0; i < 4; ++i) {
        float r0 = p0[i] + br0;
        float r1 = p1[i] + br1;
        float cf = 1.0f / (1.0f + expf(-(p2[i] + bc)));
        float sc = sqrtf(fmaf(r0, r0, r1 * r1)) * cf;
        q0[i] = r0; q1[i] = r1; qc[i] = cf; qs[i] = __float_as_uint(sc);
    }

    const int v = b * (HWn / 4) + g;   // float4-granular index
    reinterpret_cast<float4*>(g_reg0)[v] = r0v;
    reinterpret_cast<float4*>(g_reg1)[v] = r1v;
    reinterpret_cast<float4*>(g_conf)[v] = cfv;
    reinterpret_cast<uint4*>(g_sbits)[v] = sbv;
}

// ---------------------------------------------------------------------------
// Selection stage 1: 128 blocks (16 batches x 8 segments), 256 threads, 2048
// scores per block (8/thread, register-resident). 8-way multiway radix
// bisection on float bit patterns (scores >= 0 so uint order == value order):
// 10 rounds of 3 bits, 7 thresholds/round, per-thread counts packed into
// 16-bit fields -> 4 REDUX + one cross-warp shfl tree. Threshold P resolves
// bits [31:2]; count(>=P) = 300 + near-prefix stragglers (exact superset of
// the segment top-300, hence of this segment's global-top-300 members).
// Survivors written to global scratch as (bits<<32 | HWn-idx) keys.
// ---------------------------------------------------------------------------
__global__ __launch_bounds__(256) void topk_stage1()
{
    const int blk  = blockIdx.x;            // 0..127
    const int b    = blk >> 3;
    const int s0   = (blk & 7) * SEGN;
    const int tid  = threadIdx.x;
    const int wid  = tid >> 5;
    const int lane = tid & 31;
    const unsigned* sb = g_sbits + b * HWn + s0;

    __shared__ uint4    wredv[8];
    __shared__ unsigned sP;
    __shared__ int      s_m;

    if (tid == 0) s_m = 0;

    unsigned v[8];
    #pragma unroll
    for (int j = 0; j < 8; ++j) v[j] = sb[tid + 256 * j];   // coalesced

    unsigned P = 0u;
    #pragma unroll
    for (int s = 29; s >= 2; s -= 3) {
        const unsigned T1 = P | (1u << s), T2 = P | (2u << s),
                       T3 = P | (3u << s), T4 = P | (4u << s),
                       T5 = P | (5u << s), T6 = P | (6u << s),
                       T7 = P | (7u << s);
        int c1=0,c2=0,c3=0,c4=0,c5=0,c6=0,c7=0;
        #pragma unroll
        for (int j = 0; j < 8; ++j) {
            const unsigned xv = v[j];
            c1 += (xv >= T1); c2 += (xv >= T2); c3 += (xv >= T3);
            c4 += (xv >= T4); c5 += (xv >= T5); c6 += (xv >= T6);
            c7 += (xv >= T7);
        }
        unsigned p0 = (unsigned)c1 | ((unsigned)c2 << 16);
        unsigned p1 = (unsigned)c3 | ((unsigned)c4 << 16);
        unsigned p2 = (unsigned)c5 | ((unsigned)c6 << 16);
        unsigned p3 = (unsigned)c7;
        p0 = __reduce_add_sync(0xFFFFFFFFu, p0);   // fields <= 256: no carry
        p1 = __reduce_add_sync(0xFFFFFFFFu, p1);
        p2 = __reduce_add_sync(0xFFFFFFFFu, p2);
        p3 = __reduce_add_sync(0xFFFFFFFFu, p3);
        if (lane == 0) wredv[wid] = make_uint4(p0, p1, p2, p3);
        __syncthreads();
        if (wid == 0) {
            uint4 q = (lane < 8) ? wredv[lane] : make_uint4(0, 0, 0, 0);
            #pragma unroll
            for (int d = 1; d < 8; d <<= 1) {       // closed within groups of 8
                q.x += __shfl_xor_sync(0xFFFFFFFFu, q.x, d);
                q.y += __shfl_xor_sync(0xFFFFFFFFu, q.y, d);
                q.z += __shfl_xor_sync(0xFFFFFFFFu, q.z, d);
                q.w += __shfl_xor_sync(0xFFFFFFFFu, q.w, d);
            }
            if (lane == 0) {                        // fields <= 2048: no carry
                const int C1 = (int)(q.x & 0xFFFFu), C2 = (int)(q.x >> 16);
                const int C3 = (int)(q.y & 0xFFFFu), C4 = (int)(q.y >> 16);
                const int C5 = (int)(q.z & 0xFFFFu), C6 = (int)(q.z >> 16);
                const int C7 = (int)q.w;
                int jj;                              // C1>=C2>=...>=C7
                if (C4 >= Kn) jj = (C6 >= Kn) ? ((C7 >= Kn) ? 7 : 6)
                                              : ((C5 >= Kn) ? 5 : 4);
                else          jj = (C2 >= Kn) ? ((C3 >= Kn) ? 3 : 2)
                                              : ((C1 >= Kn) ? 1 : 0);
                sP = P | ((unsigned)jj << s);
            }
        }
        __syncthreads();
        P = sP;
    }

    // ---- emit survivors (warp-aggregated atomic; ~302 expected) ----
    unsigned long long* cd = g_cand + (size_t)blk * SCAP;
    #pragma unroll
    for (int j = 0; j < 8; ++j) {
        if (v[j] >= P) {
            const int p = atomicAdd(&s_m, 1);
            if (p < SCAP) {
                const int idx = s0 + tid + 256 * j;   // batch-local index
                cd[p] = ((unsigned long long)v[j] << 32)
                      | (unsigned)(HWn - idx);        // smaller idx => bigger key
            }
        }
    }
    __syncthreads();
    if (tid == 0) g_ccnt[blk] = (s_m < SCAP) ? s_m : SCAP;
}

// ---------------------------------------------------------------------------
// Selection stage 2: 16 blocks, 512 threads. Loads the ~8*302 candidates of
// its batch into registers (7 fixed slots/thread over the 8*SCAP layout,
// zero-padded), runs the same 10-round multiway bisection for the global
// threshold, then an exact stable O(M^2) rank sort (M ~ 302) on 64-bit keys
// and the gather/write. jax.lax.top_k semantics: descending value, ties ->
// lower index (encoded in the key low word).
// ---------------------------------------------------------------------------
__global__ __launch_bounds__(512) void topk_stage2(float* __restrict__ out)
{
    const int b    = blockIdx.x;
    const int tid  = threadIdx.x;
    const int wid  = tid >> 5;
    const int lane = tid & 31;

    __shared__ uint4    wredv[16];
    __shared__ int      cnt8[8];
    __shared__ unsigned sP;
    __shared__ int      s_m;
    __shared__ unsigned long long ckey[CAPF];

    if (tid == 0) s_m = 0;
    if (tid < 8)  cnt8[tid] = g_ccnt[b * 8 + tid];
    __syncthreads();

    unsigned uh[NS2], ul[NS2];
    #pragma unroll
    for (int j = 0; j < NS2; ++j) {
        const int slot = tid + 512 * j;              // < 3584 = 8*SCAP
        const int sg   = slot / SCAP;
        const int pos  = slot - sg * SCAP;
        unsigned long long k = 0ULL;
        if (pos < cnt8[sg]) k = g_cand[(size_t)(b * 8 + sg) * SCAP + pos];
        uh[j] = (unsigned)(k >> 32);
        ul[j] = (unsigned)k;
    }

    unsigned P = 0u;
    #pragma unroll
    for (int s = 29; s >= 2; s -= 3) {
        const unsigned T1 = P | (1u << s), T2 = P | (2u << s),
                       T3 = P | (3u << s), T4 = P | (4u << s),
                       T5 = P | (5u << s), T6 = P | (6u << s),
                       T7 = P | (7u << s);
        int c1=0,c2=0,c3=0,c4=0,c5=0,c6=0,c7=0;
        #pragma unroll
        for (int j = 0; j < NS2; ++j) {
            const unsigned xv = uh[j];
            c1 += (xv >= T1); c2 += (xv >= T2); c3 += (xv >= T3);
            c4 += (xv >= T4); c5 += (xv >= T5); c6 += (xv >= T6);
            c7 += (xv >= T7);
        }
        unsigned p0 = (unsigned)c1 | ((unsigned)c2 << 16);
        unsigned p1 = (unsigned)c3 | ((unsigned)c4 << 16);
        unsigned p2 = (unsigned)c5 | ((unsigned)c6 << 16);
        unsigned p3 = (unsigned)c7;
        p0 = __reduce_add_sync(0xFFFFFFFFu, p0);
        p1 = __reduce_add_sync(0xFFFFFFFFu, p1);
        p2 = __reduce_add_sync(0xFFFFFFFFu, p2);
        p3 = __reduce_add_sync(0xFFFFFFFFu, p3);
        if (lane == 0) wredv[wid] = make_uint4(p0, p1, p2, p3);
        __syncthreads();
        if (wid == 0) {
            uint4 q = (lane < 16) ? wredv[lane] : make_uint4(0, 0, 0, 0);
            #pragma unroll
            for (int d = 1; d < 16; d <<= 1) {      // closed within groups of 16
                q.x += __shfl_xor_sync(0xFFFFFFFFu, q.x, d);
                q.y += __shfl_xor_sync(0xFFFFFFFFu, q.y, d);
                q.z += __shfl_xor_sync(0xFFFFFFFFu, q.z, d);
                q.w += __shfl_xor_sync(0xFFFFFFFFu, q.w, d);
            }
            if (lane == 0) {                        // fields <= 3584: no carry
                const int C1 = (int)(q.x & 0xFFFFu), C2 = (int)(q.x >> 16);
                const int C3 = (int)(q.y & 0xFFFFu), C4 = (int)(q.y >> 16);
                const int C5 = (int)(q.z & 0xFFFFu), C6 = (int)(q.z >> 16);
                const int C7 = (int)q.w;
                int jj;
                if (C4 >= Kn) jj = (C6 >= Kn) ? ((C7 >= Kn) ? 7 : 6)
                                              : ((C5 >= Kn) ? 5 : 4);
                else          jj = (C2 >= Kn) ? ((C3 >= Kn) ? 3 : 2)
                                              : ((C1 >= Kn) ? 1 : 0);
                sP = P | ((unsigned)jj << s);
            }
        }
        __syncthreads();
        P = sP;
    }

    // ---- collect final candidates (>= P; ul!=0 excludes padding) ----
    #pragma unroll
    for (int j = 0; j < NS2; ++j) {
        if (uh[j] >= P && ul[j]) {
            const int p = atomicAdd(&s_m, 1);
            if (p < CAPF)
                ckey[p] = ((unsigned long long)uh[j] << 32) | ul[j];
        }
    }
    __syncthreads();
    const int M = (s_m < CAPF) ? s_m : CAPF;

    // ---- stable rank sort (broadcast SMEM reads) + gather + write ----
    for (int i = tid; i < M; i += 512) {
        const unsigned long long mk = ckey[i];
        int rank = 0;
        #pragma unroll 4
        for (int j = 0; j < M; ++j) rank += (ckey[j] > mk);
        if (rank < Kn) {
            const int k = HWn - (int)(mk & 0xFFFFFFFFu);
            float* o = out + ((size_t)b * Kn + rank) * 3;
            o[0] = (float)(k / Hn) + g_reg0[b * HWn + k];
            o[1] = (float)(k % Hn) + g_reg1[b * HWn + k];
            o[2] = g_conf[b * HWn + k];
        }
    }
}

// ---------------------------------------------------------------------------
extern "C" void kernel_launch(void* const* d_in, const int* in_sizes, int n_in,
                              void* d_out, int out_size)
{
    const float* x      = (const float*)d_in[0];  // (16,256,128,128)
    const float* w_reg  = (const float*)d_in[1];  // (2,256)
    const float* b_reg  = (const float*)d_in[2];  // (2,)
    const float* w_conf = (const float*)d_in[3];  // (1,256)
    const float* b_conf = (const float*)d_in[4];  // (1,)
    float*       out    = (float*)d_out;          // (16,300,3)

    score_kernel<<<256, 256>>>(x, w_reg, b_reg, w_conf, b_conf);
    topk_stage1<<<Bn * SEGS, 256>>>();
    topk_stage2<<<Bn, 512>>>(out);
}